// round 5
// baseline (speedup 1.0000x reference)
#include <cuda_runtime.h>
#include <cuda_bf16.h>
#include <math.h>
#include <stdint.h>

// ---------------- constants ----------------
#define BATCH 32
#define LSEQ  196
#define MROWS (BATCH*LSEQ) // 6272
#define DMODEL 512
#define DINNER 256
#define DSTATE 16
#define DTRANK 16
#define NHEAD 8
#define HDIM 64
#define KPATCH 768

// ---------------- scratch ----------------
__device__ __align__(256) __nv_bfloat16 g_ah[MROWS*KPATCH];  // activation hi (reused)
__device__ __align__(256) __nv_bfloat16 g_al[MROWS*KPATCH];  // activation lo
__device__ __align__(256) __nv_bfloat16 g_mh[MROWS*4*DMODEL];// mlp mid hi
__device__ __align__(256) __nv_bfloat16 g_ml[MROWS*4*DMODEL];// mlp mid lo
__device__ __align__(256) __nv_bfloat16 g_wh[4*DMODEL*DMODEL];// weight hi (reused)
__device__ __align__(256) __nv_bfloat16 g_wl[4*DMODEL*DMODEL];// weight lo
__device__ __align__(256) float g_t   [MROWS*DMODEL];
__device__ __align__(256) float g_xz  [MROWS*DMODEL];
__device__ __align__(256) float g_xmz [MROWS*DMODEL];
__device__ __align__(256) float g_dt  [MROWS*DINNER];
__device__ __align__(256) float g_Bm  [MROWS*DSTATE];
__device__ __align__(256) float g_Cm  [MROWS*DSTATE];
__device__ __align__(256) float g_qkv [MROWS*3*DMODEL];
__device__ __align__(256) float g_tbar[BATCH*DMODEL];

// ---------------- helpers ----------------
__device__ __forceinline__ uint32_t cvta_s(const void* p) {
    uint32_t a;
    asm("{ .reg .u64 t; cvta.to.shared.u64 t, %1; cvt.u32.u64 %0, t; }" : "=r"(a) : "l"(p));
    return a;
}
__device__ __forceinline__ void fsplit(float x, __nv_bfloat16& h, __nv_bfloat16& l) {
    h = __float2bfloat16(x);
    l = __float2bfloat16(x - __bfloat162float(h));
}

#define LDSM4(R0,R1,R2,R3,ADDR) \
    asm volatile("ldmatrix.sync.aligned.m8n8.x4.shared.b16 {%0,%1,%2,%3},[%4];" \
        : "=r"(R0),"=r"(R1),"=r"(R2),"=r"(R3) : "r"(ADDR))
#define CPASYNC16(DST,SRC) \
    asm volatile("cp.async.cg.shared.global [%0],[%1],16;" :: "r"(DST),"l"(SRC))
#define CPCOMMIT() asm volatile("cp.async.commit_group;")
#define CPWAIT1()  asm volatile("cp.async.wait_group 1;")
#define MMA_BF16(d, a0,a1,a2,a3, b0,b1) \
    asm volatile("mma.sync.aligned.m16n8k16.row.col.f32.bf16.bf16.f32 " \
        "{%0,%1,%2,%3},{%4,%5,%6,%7},{%8,%9},{%0,%1,%2,%3};" \
        : "+f"(d[0]),"+f"(d[1]),"+f"(d[2]),"+f"(d[3]) \
        : "r"(a0),"r"(a1),"r"(a2),"r"(a3),"r"(b0),"r"(b1))

// ---------------- weight split ----------------
__global__ void wsplit_k(const float* __restrict__ w, int n) {
    int i = (blockIdx.x * blockDim.x + threadIdx.x) * 4;
    if (i >= n) return;
    float4 v = *(const float4*)(w + i);
    __nv_bfloat16 h0,l0,h1,l1,h2,l2,h3,l3;
    fsplit(v.x,h0,l0); fsplit(v.y,h1,l1); fsplit(v.z,h2,l2); fsplit(v.w,h3,l3);
    g_wh[i]=h0; g_wh[i+1]=h1; g_wh[i+2]=h2; g_wh[i+3]=h3;
    g_wl[i]=l0; g_wl[i+1]=l1; g_wl[i+2]=l2; g_wl[i+3]=l3;
}

// ---------------- im2col (split output) ----------------
__global__ void im2col_k(const float* __restrict__ x) {
    int idx = blockIdx.x * blockDim.x + threadIdx.x;
    if (idx >= MROWS*KPATCH) return;
    int k = idx % KPATCH;
    int m = idx / KPATCH;
    int b = m / LSEQ, l = m % LSEQ;
    int ph = l / 14, pw = l % 14;
    int c = k / 256, rem = k % 256;
    int i = rem / 16, j = rem % 16;
    float v = x[(((size_t)b*3 + c)*224 + (ph*16 + i))*224 + (pw*16 + j)];
    __nv_bfloat16 h, lo; fsplit(v, h, lo);
    g_ah[idx] = h; g_al[idx] = lo;
}

// ---------------- 3x-bf16 tensor-core GEMM (cp.async + ldmatrix) ----------------
// C[M,N] = A[M,K] @ W[N,K]^T ; A,W pre-split into (hi,lo) bf16.
// BM=128, BN=64, BK=32, 3-stage pipeline. 8 warps, warp tile 32x32.
#define ACT_NONE 0
#define ACT_GELU 1
#define ROWB 80            // bytes per smem row (32 bf16 = 64B data + 16B pad)
#define STG_A 10240        // 128 rows * 80
#define STG_W 5120         // 64 rows * 80
#define STG_BYTES 30720    // Ah + Al + Wh + Wl
#define GEMM_SMEM (3*STG_BYTES)

__device__ __forceinline__ void stage_load(
    uint32_t smb, int stage,
    const __nv_bfloat16* __restrict__ Ah, const __nv_bfloat16* __restrict__ Al,
    const __nv_bfloat16* __restrict__ Wh, const __nv_bfloat16* __restrict__ Wl,
    int m0, int n0, int K, int kt, int tid)
{
    uint32_t sb = smb + stage*STG_BYTES;
    size_t koff = (size_t)kt*32;
#pragma unroll
    for (int j = 0; j < 2; j++) {
        int ch = tid*2 + j;          // 0..511
        int row = ch >> 2, c = ch & 3;
        size_t g = (size_t)(m0+row)*K + koff + c*8;
        CPASYNC16(sb + row*ROWB + c*16,          Ah + g);
        CPASYNC16(sb + STG_A + row*ROWB + c*16,  Al + g);
    }
    {
        int row = tid >> 2, c = tid & 3;
        size_t g = (size_t)(n0+row)*K + koff + c*8;
        CPASYNC16(sb + 2*STG_A + row*ROWB + c*16,         Wh + g);
        CPASYNC16(sb + 2*STG_A + STG_W + row*ROWB + c*16, Wl + g);
    }
}

template<int ACT, bool BIAS, bool RES, bool SPLIT>
__global__ void __launch_bounds__(256, 2)
mma3_k(const __nv_bfloat16* __restrict__ Ah, const __nv_bfloat16* __restrict__ Al,
       const __nv_bfloat16* __restrict__ Wh, const __nv_bfloat16* __restrict__ Wl,
       const float* __restrict__ bias, float* __restrict__ C,
       __nv_bfloat16* __restrict__ Ch, __nv_bfloat16* __restrict__ Cl,
       int N, int K)
{
    extern __shared__ char smemraw[];
    uint32_t smb = cvta_s(smemraw);
    int tid = threadIdx.x, wid = tid >> 5, lane = tid & 31;
    int wm = (wid >> 1) * 32, wn = (wid & 1) * 32;
    int qr = lane >> 2, qc = lane & 3;
    int m0 = blockIdx.y * 128, n0 = blockIdx.x * 64;

    float acc[2][4][4];
#pragma unroll
    for (int a = 0; a < 2; a++)
#pragma unroll
        for (int b = 0; b < 4; b++)
#pragma unroll
            for (int c = 0; c < 4; c++) acc[a][b][c] = 0.f;

    int KT = K >> 5;
    stage_load(smb, 0, Ah, Al, Wh, Wl, m0, n0, K, 0, tid); CPCOMMIT();
    stage_load(smb, 1, Ah, Al, Wh, Wl, m0, n0, K, 1, tid); CPCOMMIT();

    int lane16 = lane & 15, lh = lane >> 4;
    // relative fragment addresses (within a stage)
    uint32_t offA = (uint32_t)((wm + lane16)*ROWB + lh*16);
    uint32_t offW = (uint32_t)(2*STG_A + (wn + lh*8 + (lane & 7))*ROWB + ((lane >> 3) & 1)*16);

    for (int kt = 0; kt < KT; kt++) {
        CPWAIT1();
        __syncthreads();
        uint32_t sb = smb + (kt % 3)*STG_BYTES;
        uint32_t aAh = sb + offA;
        uint32_t aAl = aAh + STG_A;
        uint32_t aW  = sb + offW;
#pragma unroll
        for (int s = 0; s < 2; s++) {
            uint32_t so = s*32;
            uint32_t ah[2][4], al[2][4];
            LDSM4(ah[0][0],ah[0][1],ah[0][2],ah[0][3], aAh + so);
            LDSM4(ah[1][0],ah[1][1],ah[1][2],ah[1][3], aAh + 16*ROWB + so);
            LDSM4(al[0][0],al[0][1],al[0][2],al[0][3], aAl + so);
            LDSM4(al[1][0],al[1][1],al[1][2],al[1][3], aAl + 16*ROWB + so);
#pragma unroll
            for (int p = 0; p < 2; p++) {
                uint32_t bh[4], bl[4];
                LDSM4(bh[0],bh[1],bh[2],bh[3], aW + p*16*ROWB + so);
                LDSM4(bl[0],bl[1],bl[2],bl[3], aW + STG_W + p*16*ROWB + so);
#pragma unroll
                for (int mt = 0; mt < 2; mt++) {
                    MMA_BF16(acc[mt][2*p  ], ah[mt][0],ah[mt][1],ah[mt][2],ah[mt][3], bh[0],bh[1]);
                    MMA_BF16(acc[mt][2*p  ], ah[mt][0],ah[mt][1],ah[mt][2],ah[mt][3], bl[0],bl[1]);
                    MMA_BF16(acc[mt][2*p  ], al[mt][0],al[mt][1],al[mt][2],al[mt][3], bh[0],bh[1]);
                    MMA_BF16(acc[mt][2*p+1], ah[mt][0],ah[mt][1],ah[mt][2],ah[mt][3], bh[2],bh[3]);
                    MMA_BF16(acc[mt][2*p+1], ah[mt][0],ah[mt][1],ah[mt][2],ah[mt][3], bl[2],bl[3]);
                    MMA_BF16(acc[mt][2*p+1], al[mt][0],al[mt][1],al[mt][2],al[mt][3], bh[2],bh[3]);
                }
            }
        }
        if (kt + 2 < KT)
            stage_load(smb, (kt+2) % 3, Ah, Al, Wh, Wl, m0, n0, K, kt+2, tid);
        CPCOMMIT();
    }

    // epilogue
#pragma unroll
    for (int mt = 0; mt < 2; mt++) {
#pragma unroll
        for (int nt = 0; nt < 4; nt++) {
            int n = n0 + wn + nt*8 + qc*2;
            float2 bv = make_float2(0.f, 0.f);
            if (BIAS) bv = *(const float2*)(bias + n);
#pragma unroll
            for (int half = 0; half < 2; half++) {
                int m = m0 + wm + mt*16 + qr + half*8;
                float v0 = acc[mt][nt][half*2+0] + bv.x;
                float v1 = acc[mt][nt][half*2+1] + bv.y;
                if (ACT == ACT_GELU) {
                    float x0 = v0, x1 = v1;
                    v0 = 0.5f*x0*(1.f + tanhf(0.7978845608028654f*(x0 + 0.044715f*x0*x0*x0)));
                    v1 = 0.5f*x1*(1.f + tanhf(0.7978845608028654f*(x1 + 0.044715f*x1*x1*x1)));
                }
                if (SPLIT) {
                    __nv_bfloat16 h0,l0,h1,l1;
                    fsplit(v0,h0,l0); fsplit(v1,h1,l1);
                    *(__nv_bfloat162*)(Ch + (size_t)m*N + n) = __halves2bfloat162(h0,h1);
                    *(__nv_bfloat162*)(Cl + (size_t)m*N + n) = __halves2bfloat162(l0,l1);
                } else {
                    float* cp = C + (size_t)m*N + n;
                    if (RES) { float2 r = *(const float2*)cp; v0 += r.x; v1 += r.y; }
                    *(float2*)cp = make_float2(v0, v1);
                }
            }
        }
    }
}

// ---------------- layernorm (split output) ----------------
__global__ void ln_k(const float* __restrict__ in, const float* __restrict__ g,
                     const float* __restrict__ be,
                     __nv_bfloat16* __restrict__ oh, __nv_bfloat16* __restrict__ ol) {
    __shared__ float r1[4], r2[4];
    int m = blockIdx.x;
    const float* row = in + (size_t)m * DMODEL;
    float s = 0.f, ss = 0.f;
    for (int i = threadIdx.x; i < DMODEL; i += 128) { float v = row[i]; s += v; ss += v*v; }
#pragma unroll
    for (int off = 16; off; off >>= 1) {
        s  += __shfl_xor_sync(~0u, s, off);
        ss += __shfl_xor_sync(~0u, ss, off);
    }
    int w = threadIdx.x >> 5, lane = threadIdx.x & 31;
    if (lane == 0) { r1[w] = s; r2[w] = ss; }
    __syncthreads();
    s  = r1[0] + r1[1] + r1[2] + r1[3];
    ss = r2[0] + r2[1] + r2[2] + r2[3];
    float mean = s * (1.f/DMODEL);
    float var  = ss * (1.f/DMODEL) - mean*mean;
    float rs   = rsqrtf(var + 1e-6f);
    for (int i = threadIdx.x; i < DMODEL; i += 128) {
        float v = (row[i] - mean) * rs * g[i] + be[i];
        __nv_bfloat16 h, lo; fsplit(v, h, lo);
        oh[(size_t)m*DMODEL + i] = h;
        ol[(size_t)m*DMODEL + i] = lo;
    }
}

// ---------------- dwconv + silu ----------------
__global__ void dwconv_silu_k(const float* __restrict__ cxw, const float* __restrict__ cxb,
                              const float* __restrict__ czw, const float* __restrict__ czb) {
    int idx = blockIdx.x * blockDim.x + threadIdx.x;
    if (idx >= MROWS*DMODEL) return;
    int c = idx % DMODEL;
    int m = idx / DMODEL;
    int l = m % LSEQ;
    const float* w; float acc;
    if (c < DINNER) { w = cxw + c*4;          acc = cxb[c]; }
    else            { w = czw + (c-DINNER)*4; acc = czb[c-DINNER]; }
#pragma unroll
    for (int k = 0; k < 4; k++) {
        int lp = l - 3 + k;
        if (lp >= 0) acc += w[k] * g_xz[(size_t)(m - 3 + k)*DMODEL + c];
    }
    g_xmz[idx] = acc / (1.f + __expf(-acc));
}

// ---------------- x_proj + dt_proj + softplus ----------------
__global__ void xproj_dt_k(const float* __restrict__ xpw, const float* __restrict__ dtw,
                           const float* __restrict__ dtb) {
    int m = blockIdx.x;
    __shared__ float xs[DINNER];
    __shared__ float dtr[DTRANK];
    int tid = threadIdx.x;
    xs[tid] = g_xmz[(size_t)m*DMODEL + tid];
    __syncthreads();
    int w = tid >> 5, lane = tid & 31;
    for (int j = w; j < DTRANK + 2*DSTATE; j += 8) {
        const float* wr = xpw + j*DINNER;
        float p = 0.f;
        for (int e = lane; e < DINNER; e += 32) p += xs[e] * wr[e];
#pragma unroll
        for (int off = 16; off; off >>= 1) p += __shfl_xor_sync(~0u, p, off);
        if (lane == 0) {
            if (j < DTRANK)              dtr[j] = p;
            else if (j < DTRANK+DSTATE)  g_Bm[(size_t)m*DSTATE + (j-DTRANK)] = p;
            else                         g_Cm[(size_t)m*DSTATE + (j-DTRANK-DSTATE)] = p;
        }
    }
    __syncthreads();
    float s = dtb[tid];
#pragma unroll
    for (int r = 0; r < DTRANK; r++) s += dtr[r] * dtw[tid*DTRANK + r];
    g_dt[(size_t)m*DINNER + tid] = (s > 20.f) ? s : log1pf(__expf(s));
}

// ---------------- selective scan (independent threads, split ycat output) ----------------
__global__ void scan_k(const float* __restrict__ A_log, const float* __restrict__ Dp) {
    int gid = blockIdx.x * 32 + threadIdx.x;   // 8192 threads
    int b = gid >> 8;
    int d = gid & 255;
    float Arow[DSTATE];
#pragma unroll
    for (int n = 0; n < DSTATE; n++) Arow[n] = -__expf(A_log[d*DSTATE + n]);
    float hst[DSTATE] = {};
    float Dv = Dp[d];
    for (int l = 0; l < LSEQ; l++) {
        size_t m = (size_t)b*LSEQ + l;
        float dt = g_dt[m*DINNER + d];
        float u  = g_xmz[m*DMODEL + d];
        float du = dt * u;
        const float* Bp = g_Bm + m*DSTATE;
        const float* Cp = g_Cm + m*DSTATE;
        float acc = 0.f;
#pragma unroll
        for (int n = 0; n < DSTATE; n++) {
            float dA = __expf(dt * Arow[n]);
            hst[n] = dA * hst[n] + du * __ldg(Bp + n);
            acc += hst[n] * __ldg(Cp + n);
        }
        float y = acc + u * Dv;
        __nv_bfloat16 h, lo;
        fsplit(y, h, lo);
        g_ah[m*DMODEL + d] = h; g_al[m*DMODEL + d] = lo;
        float z = g_xmz[m*DMODEL + DINNER + d];
        fsplit(z, h, lo);
        g_ah[m*DMODEL + DINNER + d] = h; g_al[m*DMODEL + DINNER + d] = lo;
    }
}

// ---------------- attention (float4 QK, split output) ----------------
#define KSTR 72
__global__ void attn_k() {
    extern __shared__ float sm[];
    float* Ks = sm;                       // [196][72]
    float* Vs = Ks + LSEQ*KSTR;           // [196][72]
    float* Qs = Vs + LSEQ*KSTR;           // [8][64]
    float* Aw = Qs + 8*64;                // [8][196]
    int b = blockIdx.x >> 3, h = blockIdx.x & 7;
    int tid = threadIdx.x;
    const float* base = g_qkv + (size_t)b * LSEQ * (3*DMODEL);
    for (int i = tid; i < LSEQ*HDIM; i += 256) {
        int l = i / HDIM, d = i % HDIM;
        Ks[l*KSTR + d] = base[(size_t)l*(3*DMODEL) + DMODEL   + h*HDIM + d];
        Vs[l*KSTR + d] = base[(size_t)l*(3*DMODEL) + 2*DMODEL + h*HDIM + d];
    }
    __syncthreads();
    int w = tid >> 5, lane = tid & 31;
    float* qr = Qs + w*HDIM;
    float* aw = Aw + w*LSEQ;
    for (int q = w; q < LSEQ; q += 8) {
        qr[lane]      = base[(size_t)q*(3*DMODEL) + h*HDIM + lane];
        qr[lane + 32] = base[(size_t)q*(3*DMODEL) + h*HDIM + lane + 32];
        __syncwarp();
        const float4* q4 = (const float4*)qr;
        float lmax = -1e30f;
        for (int k = lane; k < LSEQ; k += 32) {
            const float4* k4 = (const float4*)(Ks + k*KSTR);
            float s = 0.f;
#pragma unroll
            for (int d = 0; d < 16; d++) {
                float4 qv = q4[d], kv = k4[d];
                s += qv.x*kv.x + qv.y*kv.y + qv.z*kv.z + qv.w*kv.w;
            }
            s *= 0.125f;
            aw[k] = s;
            lmax = fmaxf(lmax, s);
        }
#pragma unroll
        for (int off = 16; off; off >>= 1) lmax = fmaxf(lmax, __shfl_xor_sync(~0u, lmax, off));
        float lsum = 0.f;
        for (int k = lane; k < LSEQ; k += 32) { float e = __expf(aw[k] - lmax); aw[k] = e; lsum += e; }
#pragma unroll
        for (int off = 16; off; off >>= 1) lsum += __shfl_xor_sync(~0u, lsum, off);
        float inv = 1.f / lsum;
        __syncwarp();
        float o0 = 0.f, o1 = 0.f;
        for (int k = 0; k < LSEQ; k++) {
            float a = aw[k];
            o0 += a * Vs[k*KSTR + lane];
            o1 += a * Vs[k*KSTR + lane + 32];
        }
        o0 *= inv; o1 *= inv;
        size_t orow = ((size_t)(b*LSEQ + q))*DMODEL + h*HDIM;
        __nv_bfloat16 hh, ll;
        fsplit(o0, hh, ll); g_ah[orow + lane]      = hh; g_al[orow + lane]      = ll;
        fsplit(o1, hh, ll); g_ah[orow + lane + 32] = hh; g_al[orow + lane + 32] = ll;
        __syncwarp();
    }
}

// ---------------- mean over sequence ----------------
__global__ void meanrow_k() {
    int b = blockIdx.x, d = threadIdx.x;
    float s = 0.f;
    for (int l = 0; l < LSEQ; l++) s += g_t[((size_t)b*LSEQ + l)*DMODEL + d];
    g_tbar[b*DMODEL + d] = s * (1.f/LSEQ);
}

// ---------------- head + fc ----------------
__global__ void headfc_k(const float* __restrict__ hw, const float* __restrict__ hb,
                         const float* __restrict__ fw, const float* __restrict__ fb,
                         float* __restrict__ out) {
    int b = blockIdx.x;
    __shared__ float ts[DMODEL];
    __shared__ float ps[1024];
    int tid = threadIdx.x;
    ts[tid]       = g_tbar[b*DMODEL + tid];
    ts[tid + 256] = g_tbar[b*DMODEL + tid + 256];
    __syncthreads();
    int w = tid >> 5, lane = tid & 31;
    for (int j = w; j < 1024; j += 8) {
        const float* wr = hw + j*DMODEL;
        float p = 0.f;
        for (int e = lane; e < DMODEL; e += 32) p += ts[e] * wr[e];
#pragma unroll
        for (int off = 16; off; off >>= 1) p += __shfl_xor_sync(~0u, p, off);
        if (lane == 0) ps[j] = p + hb[j];
    }
    __syncthreads();
    if (w == 0) {
        for (int c = 0; c < 4; c++) {
            float p = 0.f;
            for (int e = lane; e < 1024; e += 32) p += ps[e] * fw[c*1024 + e];
#pragma unroll
            for (int off = 16; off; off >>= 1) p += __shfl_xor_sync(~0u, p, off);
            if (lane == 0) out[b*4 + c] = p + fb[c];
        }
    }
}

// ---------------- launch ----------------
extern "C" void kernel_launch(void* const* d_in, const int* in_sizes, int n_in,
                              void* d_out, int out_size) {
    const float* x        = (const float*)d_in[0];
    const float* patch_w  = (const float*)d_in[1];
    const float* patch_b  = (const float*)d_in[2];
    const float* ln1_g    = (const float*)d_in[3];
    const float* ln1_b    = (const float*)d_in[4];
    const float* in_proj  = (const float*)d_in[5];
    const float* convx_w  = (const float*)d_in[6];
    const float* convx_b  = (const float*)d_in[7];
    const float* convz_w  = (const float*)d_in[8];
    const float* convz_b  = (const float*)d_in[9];
    const float* x_proj_w = (const float*)d_in[10];
    const float* dt_proj_w= (const float*)d_in[11];
    const float* dt_proj_b= (const float*)d_in[12];
    const float* A_log    = (const float*)d_in[13];
    const float* Dp       = (const float*)d_in[14];
    const float* out_proj = (const float*)d_in[15];
    const float* ln2_g    = (const float*)d_in[16];
    const float* ln2_b    = (const float*)d_in[17];
    const float* qkv_w    = (const float*)d_in[18];
    const float* attn_pw  = (const float*)d_in[19];
    const float* ln3_g    = (const float*)d_in[20];
    const float* ln3_b    = (const float*)d_in[21];
    const float* mlp_w1   = (const float*)d_in[22];
    const float* mlp_b1   = (const float*)d_in[23];
    const float* mlp_w2   = (const float*)d_in[24];
    const float* mlp_b2   = (const float*)d_in[25];
    const float* head_w   = (const float*)d_in[26];
    const float* head_b   = (const float*)d_in[27];
    const float* fc_w     = (const float*)d_in[28];
    const float* fc_b     = (const float*)d_in[29];

    __nv_bfloat16 *ah, *al, *mh, *ml, *wh, *wl;
    float *t, *xz, *qkv;
    cudaGetSymbolAddress((void**)&ah, g_ah);
    cudaGetSymbolAddress((void**)&al, g_al);
    cudaGetSymbolAddress((void**)&mh, g_mh);
    cudaGetSymbolAddress((void**)&ml, g_ml);
    cudaGetSymbolAddress((void**)&wh, g_wh);
    cudaGetSymbolAddress((void**)&wl, g_wl);
    cudaGetSymbolAddress((void**)&t,  g_t);
    cudaGetSymbolAddress((void**)&xz, g_xz);
    cudaGetSymbolAddress((void**)&qkv,g_qkv);

    const int ATTN_SMEM = (LSEQ*KSTR*2 + 8*64 + 8*LSEQ) * (int)sizeof(float);
    cudaFuncSetAttribute(attn_k, cudaFuncAttributeMaxDynamicSharedMemorySize, ATTN_SMEM);
    cudaFuncSetAttribute(mma3_k<0,1,0,0>, cudaFuncAttributeMaxDynamicSharedMemorySize, GEMM_SMEM);
    cudaFuncSetAttribute(mma3_k<0,0,0,0>, cudaFuncAttributeMaxDynamicSharedMemorySize, GEMM_SMEM);
    cudaFuncSetAttribute(mma3_k<0,0,1,0>, cudaFuncAttributeMaxDynamicSharedMemorySize, GEMM_SMEM);
    cudaFuncSetAttribute(mma3_k<1,1,0,1>, cudaFuncAttributeMaxDynamicSharedMemorySize, GEMM_SMEM);
    cudaFuncSetAttribute(mma3_k<0,1,1,0>, cudaFuncAttributeMaxDynamicSharedMemorySize, GEMM_SMEM);

    dim3 g512 (DMODEL/64,   MROWS/128);   // (8, 49)
    dim3 g1536(3*DMODEL/64, MROWS/128);   // (24, 49)
    dim3 g2048(4*DMODEL/64, MROWS/128);   // (32, 49)

    // 1. patch embed
    wsplit_k<<<(DMODEL*KPATCH/4 + 255)/256, 256>>>(patch_w, DMODEL*KPATCH);
    im2col_k<<<(MROWS*KPATCH + 255)/256, 256>>>(x);
    mma3_k<0,1,0,0><<<g512, 256, GEMM_SMEM>>>(ah, al, wh, wl, patch_b, t, nullptr, nullptr, DMODEL, KPATCH);
    // 2. mamba block
    ln_k<<<MROWS, 128>>>(t, ln1_g, ln1_b, ah, al);
    wsplit_k<<<(DMODEL*DMODEL/4 + 255)/256, 256>>>(in_proj, DMODEL*DMODEL);
    mma3_k<0,0,0,0><<<g512, 256, GEMM_SMEM>>>(ah, al, wh, wl, nullptr, xz, nullptr, nullptr, DMODEL, DMODEL);
    dwconv_silu_k<<<(MROWS*DMODEL)/256, 256>>>(convx_w, convx_b, convz_w, convz_b);
    xproj_dt_k<<<MROWS, 256>>>(x_proj_w, dt_proj_w, dt_proj_b);
    scan_k<<<256, 32>>>(A_log, Dp);
    wsplit_k<<<(DMODEL*DMODEL/4 + 255)/256, 256>>>(out_proj, DMODEL*DMODEL);
    mma3_k<0,0,1,0><<<g512, 256, GEMM_SMEM>>>(ah, al, wh, wl, nullptr, t, nullptr, nullptr, DMODEL, DMODEL);
    // 3. attention block
    ln_k<<<MROWS, 128>>>(t, ln2_g, ln2_b, ah, al);
    wsplit_k<<<(3*DMODEL*DMODEL/4 + 255)/256, 256>>>(qkv_w, 3*DMODEL*DMODEL);
    mma3_k<0,0,0,0><<<g1536, 256, GEMM_SMEM>>>(ah, al, wh, wl, nullptr, qkv, nullptr, nullptr, 3*DMODEL, DMODEL);
    attn_k<<<BATCH*NHEAD, 256, ATTN_SMEM>>>();
    wsplit_k<<<(DMODEL*DMODEL/4 + 255)/256, 256>>>(attn_pw, DMODEL*DMODEL);
    mma3_k<0,0,1,0><<<g512, 256, GEMM_SMEM>>>(ah, al, wh, wl, nullptr, t, nullptr, nullptr, DMODEL, DMODEL);
    // 4. MLP block
    ln_k<<<MROWS, 128>>>(t, ln3_g, ln3_b, ah, al);
    wsplit_k<<<(4*DMODEL*DMODEL/4 + 255)/256, 256>>>(mlp_w1, 4*DMODEL*DMODEL);
    mma3_k<1,1,0,1><<<g2048, 256, GEMM_SMEM>>>(ah, al, wh, wl, mlp_b1, nullptr, mh, ml, 4*DMODEL, DMODEL);
    wsplit_k<<<(4*DMODEL*DMODEL/4 + 255)/256, 256>>>(mlp_w2, 4*DMODEL*DMODEL);
    mma3_k<0,1,1,0><<<g512, 256, GEMM_SMEM>>>(mh, ml, wh, wl, mlp_b2, t, nullptr, nullptr, DMODEL, 4*DMODEL);
    // 5. head
    meanrow_k<<<BATCH, DMODEL>>>();
    headfc_k<<<BATCH, 256>>>(head_w, head_b, fc_w, fc_b, (float*)d_out);
}